// round 15
// baseline (speedup 1.0000x reference)
#include <cuda_runtime.h>
#include <cuda_bf16.h>
#include <cuda_fp16.h>
#include <cuda_fp8.h>
#include <cstdint>
#include <math.h>

#define NB 512
#define SEQ 128
#define D 256
#define NREST 65024            // NB*(SEQ-1)

#define BM 128
#define BROWS 127              // real columns per tile = one batch of rest rows
#define GRIDX 4                // NB/BM
#define GRIDY 74               // persistent: 4*74 = 296 CTAs = 2/SM (all co-resident)
#define NTILES NB              // 512 tiles, one per batch
#define TOTAL_BLOCKS (GRIDX * GRIDY)

#define SROW 272               // bytes per smem row: 256 fp8 + 16 pad (conflict-free LDSM)
#define TILE_BYTES (128 * SROW)   // 34816 (includes zero pad row 127)

// dynamic smem layout (bytes)
#define SM_A 0
#define SM_B TILE_BYTES                       // two stages: + (t&1)*TILE_BYTES
#define SM_MISC (SM_B + 2 * TILE_BYTES)
#define SM_TOTAL (SM_MISC + 2 * BM * 4 + 64 + 64 * 4)

#define LOG2E 1.4426950408889634f

// ---------------- device scratch ----------------
__device__ uint8_t g_anchors[NB * D];        // e4m3, scaled by log2e/norm
__device__ uint8_t g_rest[(size_t)NREST * D]; // e4m3, scaled by 1/norm
__device__ float g_tot[NB];
__device__ float g_pos[NB];
__device__ unsigned g_done;
__device__ volatile int g_flag[NB];

__device__ __forceinline__ uint32_t smem_u32(const void* p) {
    return (uint32_t)__cvta_generic_to_shared(p);
}
__device__ __forceinline__ void cp_async16(uint32_t dst, const void* src) {
    asm volatile("cp.async.cg.shared.global [%0], [%1], 16;" :: "r"(dst), "l"(src) : "memory");
}
__device__ __forceinline__ void cp_commit() {
    asm volatile("cp.async.commit_group;" ::: "memory");
}
template <int N>
__device__ __forceinline__ void cp_wait() {
    asm volatile("cp.async.wait_group %0;" :: "n"(N) : "memory");
}
__device__ __forceinline__ uint2 quant8(float4 a, float4 b, float scale) {
    __nv_fp8x2_storage_t q0 = __nv_cvt_float2_to_fp8x2(
        make_float2(a.x * scale, a.y * scale), __NV_SATFINITE, __NV_E4M3);
    __nv_fp8x2_storage_t q1 = __nv_cvt_float2_to_fp8x2(
        make_float2(a.z * scale, a.w * scale), __NV_SATFINITE, __NV_E4M3);
    __nv_fp8x2_storage_t q2 = __nv_cvt_float2_to_fp8x2(
        make_float2(b.x * scale, b.y * scale), __NV_SATFINITE, __NV_E4M3);
    __nv_fp8x2_storage_t q3 = __nv_cvt_float2_to_fp8x2(
        make_float2(b.z * scale, b.w * scale), __NV_SATFINITE, __NV_E4M3);
    uint2 u;
    u.x = (uint32_t)q0 | ((uint32_t)q1 << 16);
    u.y = (uint32_t)q2 | ((uint32_t)q3 << 16);
    return u;
}

// ---------------- kernel 1: anchors (scaled by log2e) + init ----------------
__global__ void anchor_kernel(const float* __restrict__ inp) {
    int gtid = blockIdx.x * 256 + threadIdx.x;     // 64 x 256 = 16384 = 512 warps
    if (gtid < NB) { g_tot[gtid] = 0.0f; g_pos[gtid] = 0.0f; g_flag[gtid] = 0; }
    if (gtid == 0) g_done = 0u;

    int w    = gtid >> 5;       // batch index 0..511
    int lane = gtid & 31;
    const float4* p = reinterpret_cast<const float4*>(inp + (size_t)w * SEQ * D) + lane * 2;
    float4 a = p[0];
    float4 b = p[1];
    float ss = a.x*a.x + a.y*a.y + a.z*a.z + a.w*a.w
             + b.x*b.x + b.y*b.y + b.z*b.z + b.w*b.w;
    #pragma unroll
    for (int o = 16; o > 0; o >>= 1) ss += __shfl_xor_sync(0xffffffffu, ss, o);
    float scale = LOG2E / fmaxf(sqrtf(ss), 1e-12f);
    *reinterpret_cast<uint2*>(g_anchors + (size_t)w * D + lane * 8) = quant8(a, b, scale);
}

// ---------------- CTA-wide: normalize one batch's 127 rest rows, release flag ----
__device__ __forceinline__ void norm_batch(const float* __restrict__ inp, int b) {
    int warp = threadIdx.x >> 5;
    int lane = threadIdx.x & 31;
    const float* srcB = inp + (size_t)b * SEQ * D;
    uint8_t* dstB = g_rest + (size_t)b * BROWS * D;

    for (int l0 = 1 + warp; l0 < SEQ; l0 += 16) {
        int l1 = l0 + 8;
        bool has1 = (l1 < SEQ);
        const float4* p0 = reinterpret_cast<const float4*>(srcB + (size_t)l0 * D) + lane * 2;
        float4 a0 = p0[0], b0 = p0[1];
        float4 a1, b1;
        if (has1) {
            const float4* p1 = reinterpret_cast<const float4*>(srcB + (size_t)l1 * D) + lane * 2;
            a1 = p1[0]; b1 = p1[1];
        } else {
            a1 = make_float4(1,0,0,0); b1 = make_float4(0,0,0,0);
        }
        float s0 = a0.x*a0.x + a0.y*a0.y + a0.z*a0.z + a0.w*a0.w
                 + b0.x*b0.x + b0.y*b0.y + b0.z*b0.z + b0.w*b0.w;
        float s1 = a1.x*a1.x + a1.y*a1.y + a1.z*a1.z + a1.w*a1.w
                 + b1.x*b1.x + b1.y*b1.y + b1.z*b1.z + b1.w*b1.w;
        #pragma unroll
        for (int o = 16; o > 0; o >>= 1) {
            s0 += __shfl_xor_sync(0xffffffffu, s0, o);
            s1 += __shfl_xor_sync(0xffffffffu, s1, o);
        }
        float sc0 = 1.0f / fmaxf(sqrtf(s0), 1e-12f);
        *reinterpret_cast<uint2*>(dstB + (size_t)(l0 - 1) * D + lane * 8) = quant8(a0, b0, sc0);
        if (has1) {
            float sc1 = 1.0f / fmaxf(sqrtf(s1), 1e-12f);
            *reinterpret_cast<uint2*>(dstB + (size_t)(l1 - 1) * D + lane * 8) = quant8(a1, b1, sc1);
        }
    }
    __syncthreads();                       // all warps' stores done (block scope)
    if (threadIdx.x == 0) {
        __threadfence();                   // cumulative release (post-bar.sync)
        g_flag[b] = 1;
    }
}

__device__ __forceinline__ void wait_flag(int j) {
    while (g_flag[j] == 0) { }
    __threadfence();                       // acquire
}

// ---------------- kernel 2: fused normalize + persistent FP8 GEMM ----------------
__global__ void __launch_bounds__(256, 2) score_kernel(float* __restrict__ out,
                                                       const float* __restrict__ inp,
                                                       const int* __restrict__ lab) {
    extern __shared__ __align__(16) char S[];

    float* sTot  = reinterpret_cast<float*>(S + SM_MISC);
    float* sPos  = sTot + BM;
    int*   sFlag = reinterpret_cast<int*>(sPos + BM);
    int*   sHist = sFlag + 16;

    int tid  = threadIdx.x;
    int lane = tid & 31;
    int warp = tid >> 5;
    int wm = (warp & 3) * 32;   // 4 warps along M
    int wn = (warp >> 2) * 64;  // 2 warps along N
    int bm = blockIdx.x * BM;
    int gy = blockIdx.y;
    int bid = blockIdx.x + blockIdx.y * GRIDX;
    int T  = (NTILES - gy + GRIDY - 1) / GRIDY;   // 7 or 6 tiles (batches)

    if (tid < BM) { sTot[tid] = 0.0f; sPos[tid] = 0.0f; }

    uint32_t smA = smem_u32(S + SM_A);
    uint32_t smB = smem_u32(S + SM_B);

    // zero the pad row (row 127) of both B stages once
    if (tid >= 32 && tid < 64) {
        int k = tid - 32;
        int st = k >> 4, c = k & 15;
        *reinterpret_cast<uint4*>(S + SM_B + st * TILE_BYTES + 127 * SROW + c * 16) =
            make_uint4(0u, 0u, 0u, 0u);
    }

    #define ISSUE_B(t_, st_)                                                        \
        do {                                                                        \
            int _j = gy + (t_) * GRIDY;                                             \
            const uint8_t* _gB = g_rest + (size_t)_j * BROWS * D;                   \
            _Pragma("unroll")                                                       \
            for (int i = 0; i < 8; i++) {                                           \
                int idx = tid + i * 256;                                            \
                if (idx < BROWS * 16) {                                             \
                    int r = idx >> 4, c = idx & 15;                                 \
                    cp_async16(smB + (st_) * TILE_BYTES + r * SROW + c * 16,        \
                               _gB + (size_t)r * D + c * 16);                       \
                }                                                                   \
            }                                                                       \
            cp_commit();                                                            \
        } while (0)

    // issue A loads (anchors written by anchor_kernel — kernel boundary orders)
    {
        const uint8_t* gA = g_anchors + (size_t)bm * D;
        #pragma unroll
        for (int i = 0; i < 8; i++) {
            int idx = tid + i * 256;
            int r = idx >> 4, c = idx & 15;
            cp_async16(smA + r * SROW + c * 16, gA + (size_t)r * D + c * 16);
        }
        cp_commit();
    }

    // normalize own batch #1 (overlaps A loads), release its flag
    norm_batch(inp, bid);

    // B prologue, gated on producer flags (batch-1 flags — set unconditionally)
    wait_flag(gy);               ISSUE_B(0, 0);
    wait_flag(gy + GRIDY);       ISSUE_B(1, 1);

    // normalize own batch #2 (overlaps B0/B1 loads)
    if (bid + TOTAL_BLOCKS < NB) norm_batch(inp, bid + TOTAL_BLOCKS);

    // row labels fixed per thread
    int qr = lane >> 2;
    int rlab[2][2];
    #pragma unroll
    for (int mf = 0; mf < 2; mf++)
        #pragma unroll
        for (int h = 0; h < 2; h++)
            rlab[mf][h] = lab[bm + wm + mf * 16 + h * 8 + qr];

    float rts[2][2] = {{0.f, 0.f}, {0.f, 0.f}};
    float rps[2][2] = {{0.f, 0.f}, {0.f, 0.f}};
    uint32_t afr[2][4], bfr[8][2];

    #pragma unroll 1
    for (int t = 0; t < T; t++) {
        int jlab = lab[gy + t * GRIDY];

        if (t + 1 < T) cp_wait<1>(); else cp_wait<0>();
        __syncthreads();

        uint32_t bBase = smB + (t & 1) * TILE_BYTES;

        float acc[2][8][4];
        #pragma unroll
        for (int mf = 0; mf < 2; mf++)
            #pragma unroll
            for (int nf = 0; nf < 8; nf++)
                #pragma unroll
                for (int r = 0; r < 4; r++) acc[mf][nf][r] = 0.0f;

        #pragma unroll
        for (int ks = 0; ks < 8; ks++) {
            #pragma unroll
            for (int mf = 0; mf < 2; mf++) {
                uint32_t addr = smA + (wm + mf * 16 + (lane & 15)) * SROW
                                    + ks * 32 + (lane >> 4) * 16;
                asm volatile("ldmatrix.sync.aligned.m8n8.x4.shared.b16 {%0,%1,%2,%3}, [%4];"
                             : "=r"(afr[mf][0]), "=r"(afr[mf][1]),
                               "=r"(afr[mf][2]), "=r"(afr[mf][3])
                             : "r"(addr));
            }
            #pragma unroll
            for (int np = 0; np < 4; np++) {
                uint32_t addr = bBase + (wn + np * 16 + (lane >> 4) * 8 + (lane & 7)) * SROW
                                      + ks * 32 + ((lane >> 3) & 1) * 16;
                asm volatile("ldmatrix.sync.aligned.m8n8.x4.shared.b16 {%0,%1,%2,%3}, [%4];"
                             : "=r"(bfr[2 * np][0]), "=r"(bfr[2 * np][1]),
                               "=r"(bfr[2 * np + 1][0]), "=r"(bfr[2 * np + 1][1])
                             : "r"(addr));
            }
            #pragma unroll
            for (int mf = 0; mf < 2; mf++)
                #pragma unroll
                for (int nf = 0; nf < 8; nf++)
                    asm volatile(
                        "mma.sync.aligned.m16n8k32.row.col.f32.e4m3.e4m3.f32 "
                        "{%0,%1,%2,%3}, {%4,%5,%6,%7}, {%8,%9}, {%0,%1,%2,%3};"
                        : "+f"(acc[mf][nf][0]), "+f"(acc[mf][nf][1]),
                          "+f"(acc[mf][nf][2]), "+f"(acc[mf][nf][3])
                        : "r"(afr[mf][0]), "r"(afr[mf][1]), "r"(afr[mf][2]), "r"(afr[mf][3]),
                          "r"(bfr[nf][0]), "r"(bfr[nf][1]));
        }

        // epilogue: acc already in log2 domain (anchors scaled by log2e) -> exp2
        #pragma unroll
        for (int mf = 0; mf < 2; mf++) {
            #pragma unroll
            for (int h = 0; h < 2; h++) {
                __half2 hs = __floats2half2_rn(0.0f, 0.0f);
                #pragma unroll
                for (int nf = 0; nf < 8; nf++) {
                    __half2 hx = __floats2half2_rn(acc[mf][nf][h * 2 + 0],
                                                   acc[mf][nf][h * 2 + 1]);
                    hs = __hadd2(hs, h2exp2(hx));
                }
                float2 f = __half22float2(hs);
                float ts = f.x + f.y;
                rts[mf][h] += ts;
                rps[mf][h] += (jlab == rlab[mf][h]) ? ts : 0.0f;
            }
        }

        __syncthreads();
        if (t + 2 < T) {
            wait_flag(gy + (t + 2) * GRIDY);
            ISSUE_B(t + 2, t & 1);
        }
    }

    // drain: quad reduction, then smem/global atomics
    #pragma unroll
    for (int mf = 0; mf < 2; mf++) {
        #pragma unroll
        for (int h = 0; h < 2; h++) {
            float ts = rts[mf][h], ps = rps[mf][h];
            ts += __shfl_xor_sync(0xffffffffu, ts, 1);
            ts += __shfl_xor_sync(0xffffffffu, ts, 2);
            ps += __shfl_xor_sync(0xffffffffu, ps, 1);
            ps += __shfl_xor_sync(0xffffffffu, ps, 2);
            if ((lane & 3) == 0) {
                int lrow = wm + mf * 16 + h * 8 + qr;
                atomicAdd(&sTot[lrow], ts);
                atomicAdd(&sPos[lrow], ps);
            }
        }
    }
    __syncthreads();
    if (tid < BM) {
        atomicAdd(&g_tot[bm + tid], sTot[tid]);
        atomicAdd(&g_pos[bm + tid], sPos[tid]);
    }

    // ---- fused finalize: last CTA computes the loss ----
    __threadfence();
    __syncthreads();
    if (tid == 0) {
        unsigned v = atomicAdd(&g_done, 1u);
        sFlag[0] = (v == TOTAL_BLOCKS - 1) ? 1 : 0;
    }
    __syncthreads();
    if (sFlag[0]) {
        __threadfence();
        if (tid < 64) sHist[tid] = 0;
        __syncthreads();
        int l0 = lab[tid], l1 = lab[tid + 256];
        atomicAdd(&sHist[l0], 1);
        atomicAdd(&sHist[l1], 1);
        __syncthreads();
        // every tile adds exp2(0)=1 to tot; same-label tiles add 1 to pos
        float v = (logf(g_tot[tid]       - 512.0f) - logf(g_pos[tid]       - (float)sHist[l0]))
                + (logf(g_tot[tid + 256] - 512.0f) - logf(g_pos[tid + 256] - (float)sHist[l1]));
        #pragma unroll
        for (int o = 16; o > 0; o >>= 1) v += __shfl_xor_sync(0xffffffffu, v, o);
        float* red = sTot;   // reuse
        if (lane == 0) red[warp] = v;
        __syncthreads();
        if (tid == 0) {
            float s = 0.0f;
            #pragma unroll
            for (int w = 0; w < 8; w++) s += red[w];
            out[0] = s * (1.0f / 512.0f);
        }
    }
}

// ---------------- launch ----------------
extern "C" void kernel_launch(void* const* d_in, const int* in_sizes, int n_in,
                              void* d_out, int out_size) {
    const float* inp = (const float*)d_in[0];
    const int*   lab = (const int*)d_in[1];
    float*       out = (float*)d_out;

    cudaFuncSetAttribute(score_kernel, cudaFuncAttributeMaxDynamicSharedMemorySize, SM_TOTAL);

    anchor_kernel<<<64, 256>>>(inp);
    score_kernel<<<dim3(GRIDX, GRIDY), 256, SM_TOTAL>>>(out, inp, lab);
}

// round 16
// speedup vs baseline: 1.0766x; 1.0766x over previous
#include <cuda_runtime.h>
#include <cuda_bf16.h>
#include <cuda_fp16.h>
#include <cuda_fp8.h>
#include <cstdint>
#include <math.h>

#define NB 512
#define SEQ 128
#define D 256
#define NREST 65024            // NB*(SEQ-1)

#define BM 128
#define BROWS 127              // rest rows per batch
#define GRIDX 4                // NB/BM
#define GRIDY 111              // 4*111 = 444 CTAs = 3/SM, persistent
#define NTILES2 1024           // 512 batches x 2 half-tiles (64 cols each)
#define TOTAL_BLOCKS (GRIDX * GRIDY)

#define SROW 272               // bytes per smem row: 256 fp8 + 16 pad (conflict-free LDSM)
#define A_BYTES (BM * SROW)    // 34816
#define BSTAGE (64 * SROW)     // 17408 per B stage (64 rows)

// dynamic smem layout (bytes)
#define SM_A 0
#define SM_B A_BYTES                          // two stages: + st*BSTAGE
#define SM_MISC (SM_B + 2 * BSTAGE)           // 69632
#define SM_TOTAL (SM_MISC + 2 * BM * 4 + 64 + 64 * 4)

#define LOG2E 1.4426950408889634f

// ---------------- device scratch ----------------
__device__ uint8_t g_anchors[NB * D];        // e4m3, scaled by log2e/norm
__device__ uint8_t g_rest[(size_t)NREST * D]; // e4m3, scaled by 1/norm
__device__ int   g_labels[NB];
__device__ float g_tot[NB];
__device__ float g_pos[NB];
__device__ unsigned g_done;

__device__ __forceinline__ uint32_t smem_u32(const void* p) {
    return (uint32_t)__cvta_generic_to_shared(p);
}
__device__ __forceinline__ void cp_async16(uint32_t dst, const void* src) {
    asm volatile("cp.async.cg.shared.global [%0], [%1], 16;" :: "r"(dst), "l"(src) : "memory");
}
__device__ __forceinline__ void cp_commit() {
    asm volatile("cp.async.commit_group;" ::: "memory");
}
template <int N>
__device__ __forceinline__ void cp_wait() {
    asm volatile("cp.async.wait_group %0;" :: "n"(N) : "memory");
}
__device__ __forceinline__ uint2 quant8(float4 a, float4 b, float scale) {
    __nv_fp8x2_storage_t q0 = __nv_cvt_float2_to_fp8x2(
        make_float2(a.x * scale, a.y * scale), __NV_SATFINITE, __NV_E4M3);
    __nv_fp8x2_storage_t q1 = __nv_cvt_float2_to_fp8x2(
        make_float2(a.z * scale, a.w * scale), __NV_SATFINITE, __NV_E4M3);
    __nv_fp8x2_storage_t q2 = __nv_cvt_float2_to_fp8x2(
        make_float2(b.x * scale, b.y * scale), __NV_SATFINITE, __NV_E4M3);
    __nv_fp8x2_storage_t q3 = __nv_cvt_float2_to_fp8x2(
        make_float2(b.z * scale, b.w * scale), __NV_SATFINITE, __NV_E4M3);
    uint2 u;
    u.x = (uint32_t)q0 | ((uint32_t)q1 << 16);
    u.y = (uint32_t)q2 | ((uint32_t)q3 << 16);
    return u;
}

// ---------------- kernel 1: normalize + init (anchors folded with log2e) --------
__global__ void normalize_kernel(const float* __restrict__ inp, const int* __restrict__ lab) {
    int gtid = blockIdx.x * 256 + threadIdx.x;
    if (gtid < NB) { g_tot[gtid] = 0.0f; g_pos[gtid] = 0.0f; g_labels[gtid] = lab[gtid]; }
    if (gtid == 0) g_done = 0u;

    int row  = blockIdx.x * 8 + (threadIdx.x >> 5);
    int lane = threadIdx.x & 31;
    const float4* p = reinterpret_cast<const float4*>(inp + (size_t)row * D) + lane * 2;
    float4 a = p[0];
    float4 b = p[1];
    float ss = a.x*a.x + a.y*a.y + a.z*a.z + a.w*a.w
             + b.x*b.x + b.y*b.y + b.z*b.z + b.w*b.w;
    #pragma unroll
    for (int o = 16; o > 0; o >>= 1) ss += __shfl_xor_sync(0xffffffffu, ss, o);
    float inv = 1.0f / fmaxf(sqrtf(ss), 1e-12f);

    int bidx = row >> 7;
    int l    = row & 127;
    if (l == 0) {
        *reinterpret_cast<uint2*>(g_anchors + (size_t)bidx * D + lane * 8)
            = quant8(a, b, inv * LOG2E);
    } else {
        *reinterpret_cast<uint2*>(g_rest + (size_t)(bidx * BROWS + (l - 1)) * D + lane * 8)
            = quant8(a, b, inv);
    }
}

// ---------------- kernel 2: persistent FP8 GEMM, 3 CTAs/SM, half-batch tiles -----
__global__ void __launch_bounds__(256, 3) score_kernel(float* __restrict__ out) {
    extern __shared__ __align__(16) char S[];

    float* sTot  = reinterpret_cast<float*>(S + SM_MISC);
    float* sPos  = sTot + BM;
    int*   sFlag = reinterpret_cast<int*>(sPos + BM);
    int*   sHist = sFlag + 16;

    int tid  = threadIdx.x;
    int lane = tid & 31;
    int warp = tid >> 5;
    int wm = (warp & 3) * 32;   // 4 warps along M (m32 each)
    int wn = (warp >> 2) * 32;  // 2 warps along N (n32 each)
    int bm = blockIdx.x * BM;
    int gy = blockIdx.y;
    int T  = (NTILES2 - gy + GRIDY - 1) / GRIDY;   // 10 (gy<25) or 9

    if (tid < BM) { sTot[tid] = 0.0f; sPos[tid] = 0.0f; }

    uint32_t smA = smem_u32(S + SM_A);
    uint32_t smB = smem_u32(S + SM_B);

    // B half-tile load: 64 (or 63+zero) rows x 16 chunks -> 4/thread
    #define ISSUE_B(t_, st_)                                                        \
        do {                                                                        \
            int _j = gy + (t_) * GRIDY;                                             \
            int _ba = _j >> 1, _hf = _j & 1;                                        \
            const uint8_t* _gB = g_rest + ((size_t)_ba * BROWS + _hf * 64) * D;     \
            int _nch = (_hf ? 63 : 64) * 16;                                        \
            _Pragma("unroll")                                                       \
            for (int i = 0; i < 4; i++) {                                           \
                int idx = tid + i * 256;                                            \
                if (idx < _nch) {                                                   \
                    int r = idx >> 4, c = idx & 15;                                 \
                    cp_async16(smB + (st_) * BSTAGE + r * SROW + c * 16,            \
                               _gB + (size_t)r * D + c * 16);                       \
                }                                                                   \
            }                                                                       \
            if (_hf && tid < 17)                                                    \
                *reinterpret_cast<uint4*>(S + SM_B + (st_) * BSTAGE                 \
                                          + 63 * SROW + tid * 16)                   \
                    = make_uint4(0u, 0u, 0u, 0u);                                   \
            cp_commit();                                                            \
        } while (0)

    // prologue: A (128 rows x 16 chunks = 2048 -> 8/thread) + B0 in group 0; B1 group 1
    {
        const uint8_t* gA = g_anchors + (size_t)bm * D;
        #pragma unroll
        for (int i = 0; i < 8; i++) {
            int idx = tid + i * 256;
            int r = idx >> 4, c = idx & 15;
            cp_async16(smA + r * SROW + c * 16, gA + (size_t)r * D + c * 16);
        }
    }
    ISSUE_B(0, 0);        // commits group 0 (A + B0)
    ISSUE_B(1, 1);        // group 1

    // row labels fixed per thread
    int qr = lane >> 2;
    int rlab[2][2];
    #pragma unroll
    for (int mf = 0; mf < 2; mf++)
        #pragma unroll
        for (int h = 0; h < 2; h++)
            rlab[mf][h] = g_labels[bm + wm + mf * 16 + h * 8 + qr];

    float rts[2][2] = {{0.f, 0.f}, {0.f, 0.f}};
    float rps[2][2] = {{0.f, 0.f}, {0.f, 0.f}};
    uint32_t afr[2][4], bfr[4][2];

    #pragma unroll 1
    for (int t = 0; t < T; t++) {
        int jlab = g_labels[(gy + t * GRIDY) >> 1];

        if (t + 1 < T) cp_wait<1>(); else cp_wait<0>();
        __syncthreads();

        uint32_t bBase = smB + (t & 1) * BSTAGE;

        float acc[2][4][4];
        #pragma unroll
        for (int mf = 0; mf < 2; mf++)
            #pragma unroll
            for (int nf = 0; nf < 4; nf++)
                #pragma unroll
                for (int r = 0; r < 4; r++) acc[mf][nf][r] = 0.0f;

        #pragma unroll
        for (int ks = 0; ks < 8; ks++) {
            #pragma unroll
            for (int mf = 0; mf < 2; mf++) {
                uint32_t addr = smA + (wm + mf * 16 + (lane & 15)) * SROW
                                    + ks * 32 + (lane >> 4) * 16;
                asm volatile("ldmatrix.sync.aligned.m8n8.x4.shared.b16 {%0,%1,%2,%3}, [%4];"
                             : "=r"(afr[mf][0]), "=r"(afr[mf][1]),
                               "=r"(afr[mf][2]), "=r"(afr[mf][3])
                             : "r"(addr));
            }
            #pragma unroll
            for (int np = 0; np < 2; np++) {
                uint32_t addr = bBase + (wn + np * 16 + (lane >> 4) * 8 + (lane & 7)) * SROW
                                      + ks * 32 + ((lane >> 3) & 1) * 16;
                asm volatile("ldmatrix.sync.aligned.m8n8.x4.shared.b16 {%0,%1,%2,%3}, [%4];"
                             : "=r"(bfr[2 * np][0]), "=r"(bfr[2 * np][1]),
                               "=r"(bfr[2 * np + 1][0]), "=r"(bfr[2 * np + 1][1])
                             : "r"(addr));
            }
            #pragma unroll
            for (int mf = 0; mf < 2; mf++)
                #pragma unroll
                for (int nf = 0; nf < 4; nf++)
                    asm volatile(
                        "mma.sync.aligned.m16n8k32.row.col.f32.e4m3.e4m3.f32 "
                        "{%0,%1,%2,%3}, {%4,%5,%6,%7}, {%8,%9}, {%0,%1,%2,%3};"
                        : "+f"(acc[mf][nf][0]), "+f"(acc[mf][nf][1]),
                          "+f"(acc[mf][nf][2]), "+f"(acc[mf][nf][3])
                        : "r"(afr[mf][0]), "r"(afr[mf][1]), "r"(afr[mf][2]), "r"(afr[mf][3]),
                          "r"(bfr[nf][0]), "r"(bfr[nf][1]));
        }

        // epilogue: acc in log2 domain -> exp2; per-thread column share
        #pragma unroll
        for (int mf = 0; mf < 2; mf++) {
            #pragma unroll
            for (int h = 0; h < 2; h++) {
                __half2 hs = __floats2half2_rn(0.0f, 0.0f);
                #pragma unroll
                for (int nf = 0; nf < 4; nf++) {
                    __half2 hx = __floats2half2_rn(acc[mf][nf][h * 2 + 0],
                                                   acc[mf][nf][h * 2 + 1]);
                    hs = __hadd2(hs, h2exp2(hx));
                }
                float2 f = __half22float2(hs);
                float ts = f.x + f.y;
                rts[mf][h] += ts;
                rps[mf][h] += (jlab == rlab[mf][h]) ? ts : 0.0f;
            }
        }

        __syncthreads();
        if (t + 2 < T) ISSUE_B(t + 2, t & 1);
    }

    // drain: quad reduction, then smem/global atomics
    #pragma unroll
    for (int mf = 0; mf < 2; mf++) {
        #pragma unroll
        for (int h = 0; h < 2; h++) {
            float ts = rts[mf][h], ps = rps[mf][h];
            ts += __shfl_xor_sync(0xffffffffu, ts, 1);
            ts += __shfl_xor_sync(0xffffffffu, ts, 2);
            ps += __shfl_xor_sync(0xffffffffu, ps, 1);
            ps += __shfl_xor_sync(0xffffffffu, ps, 2);
            if ((lane & 3) == 0) {
                int lrow = wm + mf * 16 + h * 8 + qr;
                atomicAdd(&sTot[lrow], ts);
                atomicAdd(&sPos[lrow], ps);
            }
        }
    }
    __syncthreads();
    if (tid < BM) {
        atomicAdd(&g_tot[bm + tid], sTot[tid]);
        atomicAdd(&g_pos[bm + tid], sPos[tid]);
    }

    // ---- fused finalize: last CTA computes the loss ----
    __threadfence();
    __syncthreads();
    if (tid == 0) {
        unsigned v = atomicAdd(&g_done, 1u);
        sFlag[0] = (v == TOTAL_BLOCKS - 1) ? 1 : 0;
    }
    __syncthreads();
    if (sFlag[0]) {
        __threadfence();
        if (tid < 64) sHist[tid] = 0;
        __syncthreads();
        int l0 = g_labels[tid], l1 = g_labels[tid + 256];
        atomicAdd(&sHist[l0], 1);
        atomicAdd(&sHist[l1], 1);
        __syncthreads();
        // each batch contributes exactly one pad column: exp2(0)=1
        float v = (logf(g_tot[tid]       - 512.0f) - logf(g_pos[tid]       - (float)sHist[l0]))
                + (logf(g_tot[tid + 256] - 512.0f) - logf(g_pos[tid + 256] - (float)sHist[l1]));
        #pragma unroll
        for (int o = 16; o > 0; o >>= 1) v += __shfl_xor_sync(0xffffffffu, v, o);
        float* red = sTot;   // reuse
        if (lane == 0) red[warp] = v;
        __syncthreads();
        if (tid == 0) {
            float s = 0.0f;
            #pragma unroll
            for (int w = 0; w < 8; w++) s += red[w];
            out[0] = s * (1.0f / 512.0f);
        }
    }
}

// ---------------- launch ----------------
extern "C" void kernel_launch(void* const* d_in, const int* in_sizes, int n_in,
                              void* d_out, int out_size) {
    const float* inp = (const float*)d_in[0];
    const int*   lab = (const int*)d_in[1];
    float*       out = (float*)d_out;

    cudaFuncSetAttribute(score_kernel, cudaFuncAttributeMaxDynamicSharedMemorySize, SM_TOTAL);

    normalize_kernel<<<(NB * SEQ) / 8, 256>>>(inp, lab);
    score_kernel<<<dim3(GRIDX, GRIDY), 256, SM_TOTAL>>>(out);
}

// round 17
// speedup vs baseline: 1.1293x; 1.0489x over previous
#include <cuda_runtime.h>
#include <cuda_bf16.h>
#include <cuda_fp16.h>
#include <cuda_fp8.h>
#include <cstdint>
#include <math.h>

#define NB 512
#define SEQ 128
#define D 256
#define NREST 65024            // NB*(SEQ-1)

#define BM 128
#define BROWS 127              // real columns per tile = one batch of rest rows
#define GRIDX 4                // NB/BM
#define GRIDY 74               // persistent: 4*74 = 296 CTAs = 2/SM
#define NTILES NB              // 512 tiles, one per batch
#define TOTAL_BLOCKS (GRIDX * GRIDY)

#define SROW 272               // bytes per smem row: 256 fp8 + 16 pad (conflict-free LDSM)
#define TILE_BYTES (128 * SROW)   // 34816 (includes zero pad row 127)

// dynamic smem layout (bytes)
#define SM_A 0
#define SM_B TILE_BYTES                       // two stages: + (t&1)*TILE_BYTES
#define SM_MISC (SM_B + 2 * TILE_BYTES)
#define SM_TOTAL (SM_MISC + 2 * BM * 4 + 64 + 64 * 4)

#define LOG2E 1.4426950408889634f

// ---------------- device scratch ----------------
__device__ uint8_t g_anchors[NB * D];        // e4m3, scaled by log2e/norm
__device__ uint8_t g_rest[(size_t)NREST * D]; // e4m3, scaled by 1/norm
__device__ int   g_labels[NB];
__device__ float g_tot[NB];
__device__ float g_pos[NB];
__device__ unsigned g_done;

__device__ __forceinline__ uint32_t smem_u32(const void* p) {
    return (uint32_t)__cvta_generic_to_shared(p);
}
__device__ __forceinline__ void cp_async16(uint32_t dst, const void* src) {
    asm volatile("cp.async.cg.shared.global [%0], [%1], 16;" :: "r"(dst), "l"(src) : "memory");
}
__device__ __forceinline__ void cp_commit() {
    asm volatile("cp.async.commit_group;" ::: "memory");
}
template <int N>
__device__ __forceinline__ void cp_wait() {
    asm volatile("cp.async.wait_group %0;" :: "n"(N) : "memory");
}
__device__ __forceinline__ uint2 quant8(float4 a, float4 b, float scale) {
    __nv_fp8x2_storage_t q0 = __nv_cvt_float2_to_fp8x2(
        make_float2(a.x * scale, a.y * scale), __NV_SATFINITE, __NV_E4M3);
    __nv_fp8x2_storage_t q1 = __nv_cvt_float2_to_fp8x2(
        make_float2(a.z * scale, a.w * scale), __NV_SATFINITE, __NV_E4M3);
    __nv_fp8x2_storage_t q2 = __nv_cvt_float2_to_fp8x2(
        make_float2(b.x * scale, b.y * scale), __NV_SATFINITE, __NV_E4M3);
    __nv_fp8x2_storage_t q3 = __nv_cvt_float2_to_fp8x2(
        make_float2(b.z * scale, b.w * scale), __NV_SATFINITE, __NV_E4M3);
    uint2 u;
    u.x = (uint32_t)q0 | ((uint32_t)q1 << 16);
    u.y = (uint32_t)q2 | ((uint32_t)q3 << 16);
    return u;
}

// ---------------- kernel 1: normalize + init (anchors folded with log2e) --------
__global__ void normalize_kernel(const float* __restrict__ inp, const int* __restrict__ lab) {
    int gtid = blockIdx.x * 256 + threadIdx.x;
    if (gtid < NB) { g_tot[gtid] = 0.0f; g_pos[gtid] = 0.0f; g_labels[gtid] = lab[gtid]; }
    if (gtid == 0) g_done = 0u;

    int row  = blockIdx.x * 8 + (threadIdx.x >> 5);
    int lane = threadIdx.x & 31;
    const float4* p = reinterpret_cast<const float4*>(inp + (size_t)row * D) + lane * 2;
    float4 a = p[0];
    float4 b = p[1];
    float ss = a.x*a.x + a.y*a.y + a.z*a.z + a.w*a.w
             + b.x*b.x + b.y*b.y + b.z*b.z + b.w*b.w;
    #pragma unroll
    for (int o = 16; o > 0; o >>= 1) ss += __shfl_xor_sync(0xffffffffu, ss, o);
    float inv = 1.0f / fmaxf(sqrtf(ss), 1e-12f);

    int bidx = row >> 7;
    int l    = row & 127;
    if (l == 0) {
        *reinterpret_cast<uint2*>(g_anchors + (size_t)bidx * D + lane * 8)
            = quant8(a, b, inv * LOG2E);
    } else {
        *reinterpret_cast<uint2*>(g_rest + (size_t)(bidx * BROWS + (l - 1)) * D + lane * 8)
            = quant8(a, b, inv);
    }
}

// ---------------- kernel 2: persistent FP8 GEMM, batch-aligned tiles ----------------
__global__ void __launch_bounds__(256, 2) score_kernel(float* __restrict__ out) {
    extern __shared__ __align__(16) char S[];

    float* sTot  = reinterpret_cast<float*>(S + SM_MISC);
    float* sPos  = sTot + BM;
    int*   sFlag = reinterpret_cast<int*>(sPos + BM);
    int*   sHist = sFlag + 16;

    int tid  = threadIdx.x;
    int lane = tid & 31;
    int warp = tid >> 5;
    int wm = (warp & 3) * 32;   // 4 warps along M
    int wn = (warp >> 2) * 64;  // 2 warps along N
    int bm = blockIdx.x * BM;
    int gy = blockIdx.y;
    int T  = (NTILES - gy + GRIDY - 1) / GRIDY;   // 7 or 6 tiles (batches)

    if (tid < BM) { sTot[tid] = 0.0f; sPos[tid] = 0.0f; }

    uint32_t smA = smem_u32(S + SM_A);
    uint32_t smB = smem_u32(S + SM_B);

    // zero the pad row (row 127) of both B stages once; never overwritten
    if (tid >= 32 && tid < 64) {
        int k = tid - 32;
        int st = k >> 4, c = k & 15;
        *reinterpret_cast<uint4*>(S + SM_B + st * TILE_BYTES + 127 * SROW + c * 16) =
            make_uint4(0u, 0u, 0u, 0u);
    }

    // B tile load: 127 rows x 16 chunks = 2032 -> 8/thread
    #define ISSUE_B(t_, st_)                                                        \
        do {                                                                        \
            int _j = gy + (t_) * GRIDY;                                             \
            const uint8_t* _gB = g_rest + (size_t)_j * BROWS * D;                   \
            _Pragma("unroll")                                                       \
            for (int i = 0; i < 8; i++) {                                           \
                int idx = tid + i * 256;                                            \
                if (idx < BROWS * 16) {                                             \
                    int r = idx >> 4, c = idx & 15;                                 \
                    cp_async16(smB + (st_) * TILE_BYTES + r * SROW + c * 16,        \
                               _gB + (size_t)r * D + c * 16);                       \
                }                                                                   \
            }                                                                       \
            cp_commit();                                                            \
        } while (0)

    // prologue: A + B0 in group 0; B1 in group 1
    {
        const uint8_t* gA = g_anchors + (size_t)bm * D;
        #pragma unroll
        for (int i = 0; i < 8; i++) {
            int idx = tid + i * 256;
            int r = idx >> 4, c = idx & 15;
            cp_async16(smA + r * SROW + c * 16, gA + (size_t)r * D + c * 16);
        }
    }
    ISSUE_B(0, 0);        // commits group 0 (A + B0)
    ISSUE_B(1, 1);        // group 1

    // row labels fixed per thread for the whole kernel
    int qr = lane >> 2;
    int rlab[2][2];
    #pragma unroll
    for (int mf = 0; mf < 2; mf++)
        #pragma unroll
        for (int h = 0; h < 2; h++)
            rlab[mf][h] = g_labels[bm + wm + mf * 16 + h * 8 + qr];

    float rts[2][2] = {{0.f, 0.f}, {0.f, 0.f}};
    float rps[2][2] = {{0.f, 0.f}, {0.f, 0.f}};
    uint32_t afr[2][4], bfr[8][2];

    #pragma unroll 1
    for (int t = 0; t < T; t++) {
        int jlab = g_labels[gy + t * GRIDY];

        if (t + 1 < T) cp_wait<1>(); else cp_wait<0>();
        __syncthreads();

        uint32_t bBase = smB + (t & 1) * TILE_BYTES;

        float acc[2][8][4];
        #pragma unroll
        for (int mf = 0; mf < 2; mf++)
            #pragma unroll
            for (int nf = 0; nf < 8; nf++)
                #pragma unroll
                for (int r = 0; r < 4; r++) acc[mf][nf][r] = 0.0f;

        #pragma unroll
        for (int ks = 0; ks < 8; ks++) {
            #pragma unroll
            for (int mf = 0; mf < 2; mf++) {
                uint32_t addr = smA + (wm + mf * 16 + (lane & 15)) * SROW
                                    + ks * 32 + (lane >> 4) * 16;
                asm volatile("ldmatrix.sync.aligned.m8n8.x4.shared.b16 {%0,%1,%2,%3}, [%4];"
                             : "=r"(afr[mf][0]), "=r"(afr[mf][1]),
                               "=r"(afr[mf][2]), "=r"(afr[mf][3])
                             : "r"(addr));
            }
            #pragma unroll
            for (int np = 0; np < 4; np++) {
                uint32_t addr = bBase + (wn + np * 16 + (lane >> 4) * 8 + (lane & 7)) * SROW
                                      + ks * 32 + ((lane >> 3) & 1) * 16;
                asm volatile("ldmatrix.sync.aligned.m8n8.x4.shared.b16 {%0,%1,%2,%3}, [%4];"
                             : "=r"(bfr[2 * np][0]), "=r"(bfr[2 * np][1]),
                               "=r"(bfr[2 * np + 1][0]), "=r"(bfr[2 * np + 1][1])
                             : "r"(addr));
            }
            #pragma unroll
            for (int mf = 0; mf < 2; mf++)
                #pragma unroll
                for (int nf = 0; nf < 8; nf++)
                    asm volatile(
                        "mma.sync.aligned.m16n8k32.row.col.f32.e4m3.e4m3.f32 "
                        "{%0,%1,%2,%3}, {%4,%5,%6,%7}, {%8,%9}, {%0,%1,%2,%3};"
                        : "+f"(acc[mf][nf][0]), "+f"(acc[mf][nf][1]),
                          "+f"(acc[mf][nf][2]), "+f"(acc[mf][nf][3])
                        : "r"(afr[mf][0]), "r"(afr[mf][1]), "r"(afr[mf][2]), "r"(afr[mf][3]),
                          "r"(bfr[nf][0]), "r"(bfr[nf][1]));
        }

        // epilogue: acc already in log2 domain (anchors scaled by log2e) -> exp2;
        // per-thread column share, no shfl, no extra barrier
        #pragma unroll
        for (int mf = 0; mf < 2; mf++) {
            #pragma unroll
            for (int h = 0; h < 2; h++) {
                __half2 hs = __floats2half2_rn(0.0f, 0.0f);
                #pragma unroll
                for (int nf = 0; nf < 8; nf++) {
                    __half2 hx = __floats2half2_rn(acc[mf][nf][h * 2 + 0],
                                                   acc[mf][nf][h * 2 + 1]);
                    hs = __hadd2(hs, h2exp2(hx));
                }
                float2 f = __half22float2(hs);
                float ts = f.x + f.y;
                rts[mf][h] += ts;
                rps[mf][h] += (jlab == rlab[mf][h]) ? ts : 0.0f;
            }
        }

        // stage (t&1) fully consumed -> refill
        __syncthreads();
        if (t + 2 < T) ISSUE_B(t + 2, t & 1);
    }

    // drain: one quad reduction at the end, then smem/global atomics
    #pragma unroll
    for (int mf = 0; mf < 2; mf++) {
        #pragma unroll
        for (int h = 0; h < 2; h++) {
            float ts = rts[mf][h], ps = rps[mf][h];
            ts += __shfl_xor_sync(0xffffffffu, ts, 1);
            ts += __shfl_xor_sync(0xffffffffu, ts, 2);
            ps += __shfl_xor_sync(0xffffffffu, ps, 1);
            ps += __shfl_xor_sync(0xffffffffu, ps, 2);
            if ((lane & 3) == 0) {
                int lrow = wm + mf * 16 + h * 8 + qr;
                atomicAdd(&sTot[lrow], ts);
                atomicAdd(&sPos[lrow], ps);
            }
        }
    }
    __syncthreads();
    if (tid < BM) {
        atomicAdd(&g_tot[bm + tid], sTot[tid]);
        atomicAdd(&g_pos[bm + tid], sPos[tid]);
    }

    // ---- fused finalize: last CTA computes the loss ----
    __threadfence();
    __syncthreads();
    if (tid == 0) {
        unsigned v = atomicAdd(&g_done, 1u);
        sFlag[0] = (v == TOTAL_BLOCKS - 1) ? 1 : 0;
    }
    __syncthreads();
    if (sFlag[0]) {
        __threadfence();
        if (tid < 64) sHist[tid] = 0;
        __syncthreads();
        int l0 = g_labels[tid], l1 = g_labels[tid + 256];
        atomicAdd(&sHist[l0], 1);
        atomicAdd(&sHist[l1], 1);
        __syncthreads();
        // every tile adds exp2(0)=1 to tot; same-label tiles add 1 to pos
        float v = (logf(g_tot[tid]       - 512.0f) - logf(g_pos[tid]       - (float)sHist[l0]))
                + (logf(g_tot[tid + 256] - 512.0f) - logf(g_pos[tid + 256] - (float)sHist[l1]));
        #pragma unroll
        for (int o = 16; o > 0; o >>= 1) v += __shfl_xor_sync(0xffffffffu, v, o);
        float* red = sTot;   // reuse
        if (lane == 0) red[warp] = v;
        __syncthreads();
        if (tid == 0) {
            float s = 0.0f;
            #pragma unroll
            for (int w = 0; w < 8; w++) s += red[w];
            out[0] = s * (1.0f / 512.0f);
        }
    }
}

// ---------------- launch ----------------
extern "C" void kernel_launch(void* const* d_in, const int* in_sizes, int n_in,
                              void* d_out, int out_size) {
    const float* inp = (const float*)d_in[0];
    const int*   lab = (const int*)d_in[1];
    float*       out = (float*)d_out;

    cudaFuncSetAttribute(score_kernel, cudaFuncAttributeMaxDynamicSharedMemorySize, SM_TOTAL);

    normalize_kernel<<<(NB * SEQ) / 8, 256>>>(inp, lab);
    score_kernel<<<dim3(GRIDX, GRIDY), 256, SM_TOTAL>>>(out);
}